// round 6
// baseline (speedup 1.0000x reference)
#include <cuda_runtime.h>
#include <cuda_bf16.h>
#include <cstdint>

#define MAXN 100000
#define MAXE 1600000
#define DIM 128

// ---------------- device scratch (no allocations allowed) ----------------
__device__ float g_all[(size_t)MAXN * 512];        // [N][512] concat embeddings
__device__ float g_ego[2][(size_t)MAXN * DIM];     // ping-pong ego buffers (unnormalized)
__device__ __nv_bfloat16 g_h_hi[(size_t)MAXN * 256];   // H=[msg|ego*msg] hi
__device__ __nv_bfloat16 g_h_lo[(size_t)MAXN * 256];   // H lo residual
__device__ __nv_bfloat16 g_wbf_hi[3 * 128 * 256];  // [layer][j][k] combined W rows, bf16 hi
__device__ __nv_bfloat16 g_wbf_lo[3 * 128 * 256];  // bf16 lo (residual)
__device__ float g_bias[3 * 128];                  // gc_b + bi_b
// CSR
__device__ int   g_deg[MAXN];
__device__ int   g_off[MAXN];      // after fill: end offset of node n
__device__ int   g_bsum[256];
__device__ int2  g_ecw[MAXE];      // packed {col, weight-bits}

// ================= helpers =================
__device__ __forceinline__ uint32_t smem_u32(const void* p) {
    uint32_t a;
    asm("{ .reg .u64 t; cvta.to.shared.u64 t, %1; cvt.u32.u64 %0, t; }" : "=r"(a) : "l"(p));
    return a;
}
#define LDSM_X4(r, addr) \
    asm volatile("ldmatrix.sync.aligned.m8n8.x4.shared.b16 {%0,%1,%2,%3}, [%4];" \
        : "=r"((r)[0]), "=r"((r)[1]), "=r"((r)[2]), "=r"((r)[3]) : "r"(addr))

__device__ __forceinline__ void mma16816(float* c, const uint32_t* a, const uint32_t* b) {
    asm volatile("mma.sync.aligned.m16n8k16.row.col.f32.bf16.bf16.f32 "
        "{%0,%1,%2,%3}, {%4,%5,%6,%7}, {%8,%9}, {%0,%1,%2,%3};"
        : "+f"(c[0]), "+f"(c[1]), "+f"(c[2]), "+f"(c[3])
        : "r"(a[0]), "r"(a[1]), "r"(a[2]), "r"(a[3]), "r"(b[0]), "r"(b[1]));
}
__device__ __forceinline__ void cp_async16(uint32_t smem, const void* g, uint32_t srcsize) {
    asm volatile("cp.async.cg.shared.global [%0], [%1], 16, %2;"
                 :: "r"(smem), "l"(g), "r"(srcsize) : "memory");
}
#define CP_COMMIT() asm volatile("cp.async.commit_group;" ::: "memory")
#define CP_WAIT1() asm volatile("cp.async.wait_group 1;" ::: "memory")
#define CP_WAIT0() asm volatile("cp.async.wait_group 0;" ::: "memory")

// ---------------- prep: combined W rows -> bf16 hi/lo, bias ----------------
__global__ void prep_kernel(const float* __restrict__ gcw, const float* __restrict__ gcb,
                            const float* __restrict__ biw, const float* __restrict__ bib) {
    int t = blockIdx.x * blockDim.x + threadIdx.x;
    if (t >= 3 * 128 * 256) return;
    int i = t >> 15;
    int r = t & 32767;
    int j = r >> 8, k = r & 255;
    float v;
    if (k < 128) v = gcw[i * 16384 + j * 128 + k];
    else         v = biw[i * 16384 + j * 128 + (k - 128)];
    __nv_bfloat16 hi = __float2bfloat16_rn(v);
    __nv_bfloat16 lo = __float2bfloat16_rn(v - __bfloat162float(hi));
    g_wbf_hi[t] = hi;
    g_wbf_lo[t] = lo;
    if (k == 0) g_bias[i * 128 + j] = gcb[i * 128 + j] + bib[i * 128 + j];
}

// ---------------- init ----------------
__global__ void init_kernel(const float* __restrict__ emb, int N) {
    int t = blockIdx.x * blockDim.x + threadIdx.x;
    int total = N * 32;
    if (t >= total) return;
    int n = t / 32, f = t % 32;
    float4 v = ((const float4*)emb)[t];
    ((float4*)g_ego[0])[t] = v;
    ((float4*)g_all)[(size_t)n * 128 + f] = v;
}

// ---------------- CSR build ----------------
__global__ void csr_zero_kernel(int N) {
    for (int i = blockIdx.x * blockDim.x + threadIdx.x; i < N; i += gridDim.x * blockDim.x)
        g_deg[i] = 0;
}
__global__ void csr_hist_kernel(const int* __restrict__ ei, int E) {
    int e4 = blockIdx.x * blockDim.x + threadIdx.x;
    int E4 = E >> 2;
    for (int i = e4; i < E4; i += gridDim.x * blockDim.x) {
        int4 r = __ldg((const int4*)ei + i);
        atomicAdd(&g_deg[r.x], 1);
        atomicAdd(&g_deg[r.y], 1);
        atomicAdd(&g_deg[r.z], 1);
        atomicAdd(&g_deg[r.w], 1);
    }
    if (e4 == 0)
        for (int e = E4 * 4; e < E; e++) atomicAdd(&g_deg[ei[e]], 1);
}
__global__ void csr_scan_local_kernel(int N) {
    __shared__ int sm[1024];
    int b = blockIdx.x, t = threadIdx.x;
    int i = b * 1024 + t;
    int v = (i < N) ? g_deg[i] : 0;
    sm[t] = v;
    __syncthreads();
#pragma unroll
    for (int off = 1; off < 1024; off <<= 1) {
        int x = sm[t];
        int y = (t >= off) ? sm[t - off] : 0;
        __syncthreads();
        sm[t] = x + y;
        __syncthreads();
    }
    if (i < N) g_off[i] = sm[t] - v;   // exclusive
    if (t == 1023) g_bsum[b] = sm[t];
}
__global__ void csr_scan_bsum_kernel(int nblk) {
    __shared__ int sm[256];
    int t = threadIdx.x;
    int v = (t < nblk) ? g_bsum[t] : 0;
    sm[t] = v;
    __syncthreads();
#pragma unroll
    for (int off = 1; off < 256; off <<= 1) {
        int x = sm[t];
        int y = (t >= off) ? sm[t - off] : 0;
        __syncthreads();
        sm[t] = x + y;
        __syncthreads();
    }
    g_bsum[t] = sm[t] - v;
}
__global__ void csr_scan_add_kernel(int N) {
    int i = blockIdx.x * blockDim.x + threadIdx.x;
    if (i < N) g_off[i] += g_bsum[i >> 10];
}
// fill: uses g_off itself as cursor; afterwards g_off[n] = end offset of node n
__global__ void csr_fill_kernel(const int* __restrict__ ei, const float* __restrict__ wt, int E) {
    for (int e = blockIdx.x * blockDim.x + threadIdx.x; e < E; e += gridDim.x * blockDim.x) {
        int row = __ldg(ei + e);
        int col = __ldg(ei + E + e);
        float w = __ldg(wt + e);
        int pos = atomicAdd(&g_off[row], 1);
        g_ecw[pos] = make_int2(col, __float_as_int(w));
    }
}

// ---------------- gather: msg = A@ego, emit H=[msg|ego*msg] split-bf16 ----------------
__device__ __forceinline__ void split_pair(float x, float y, uint32_t& hi, uint32_t& lo) {
    __nv_bfloat162 h = __floats2bfloat162_rn(x, y);
    __nv_bfloat162 l = __floats2bfloat162_rn(x - __bfloat162float(h.x), y - __bfloat162float(h.y));
    hi = *reinterpret_cast<uint32_t*>(&h);
    lo = *reinterpret_cast<uint32_t*>(&l);
}

__global__ void gather_kernel(int sel, int N) {
    int g = blockIdx.x * blockDim.x + threadIdx.x;
    int n = g >> 5;
    if (n >= N) return;
    int lane = g & 31;
    int s = (n == 0) ? 0 : __ldg(g_off + n - 1);
    int e = __ldg(g_off + n);
    const float* __restrict__ ego = g_ego[sel];
    float4 acc = make_float4(0.f, 0.f, 0.f, 0.f);
    int i = s;
    for (; i + 4 <= e; i += 4) {
        int2 p0 = __ldg(g_ecw + i);
        int2 p1 = __ldg(g_ecw + i + 1);
        int2 p2 = __ldg(g_ecw + i + 2);
        int2 p3 = __ldg(g_ecw + i + 3);
        float4 v0 = __ldg((const float4*)(ego + (size_t)p0.x * DIM) + lane);
        float4 v1 = __ldg((const float4*)(ego + (size_t)p1.x * DIM) + lane);
        float4 v2 = __ldg((const float4*)(ego + (size_t)p2.x * DIM) + lane);
        float4 v3 = __ldg((const float4*)(ego + (size_t)p3.x * DIM) + lane);
        float w0 = __int_as_float(p0.y), w1 = __int_as_float(p1.y);
        float w2 = __int_as_float(p2.y), w3 = __int_as_float(p3.y);
        acc.x += w0 * v0.x; acc.y += w0 * v0.y; acc.z += w0 * v0.z; acc.w += w0 * v0.w;
        acc.x += w1 * v1.x; acc.y += w1 * v1.y; acc.z += w1 * v1.z; acc.w += w1 * v1.w;
        acc.x += w2 * v2.x; acc.y += w2 * v2.y; acc.z += w2 * v2.z; acc.w += w2 * v2.w;
        acc.x += w3 * v3.x; acc.y += w3 * v3.y; acc.z += w3 * v3.z; acc.w += w3 * v3.w;
    }
    for (; i < e; i++) {
        int2 p = __ldg(g_ecw + i);
        float w = __int_as_float(p.y);
        float4 v = __ldg((const float4*)(ego + (size_t)p.x * DIM) + lane);
        acc.x += w * v.x; acc.y += w * v.y; acc.z += w * v.z; acc.w += w * v.w;
    }
    float4 eg = __ldg((const float4*)(ego + (size_t)n * DIM) + lane);
    float4 pr = make_float4(acc.x * eg.x, acc.y * eg.y, acc.z * eg.z, acc.w * eg.w);

    char* hi_row = (char*)(g_h_hi + (size_t)n * 256);
    char* lo_row = (char*)(g_h_lo + (size_t)n * 256);
    uint2 mh, ml, ph, pl;
    split_pair(acc.x, acc.y, mh.x, ml.x);
    split_pair(acc.z, acc.w, mh.y, ml.y);
    split_pair(pr.x, pr.y, ph.x, pl.x);
    split_pair(pr.z, pr.w, ph.y, pl.y);
    *(uint2*)(hi_row + lane * 8) = mh;
    *(uint2*)(lo_row + lane * 8) = ml;
    *(uint2*)(hi_row + 256 + lane * 8) = ph;
    *(uint2*)(lo_row + 256 + lane * 8) = pl;
}

// ================= layer GEMM: pipelined cp.async + mma.sync (bf16x3) =================
// Block 128x128, K=256 in 4 stages of 64. 512 threads, 16 warps, warp tile 32x32.
#define SMEM_B_HI 0          // 65536
#define SMEM_B_LO 65536      // 65536
#define SMEM_A    131072     // 2 stages x (Ahi 16KB + Alo 16KB)
#define LK_SMEM   196608
#define EPI_ROWPART 69632    // float [128][4]  (reuses B region post-MMA)
#define EPI_SCALE   71680    // float [128]

__device__ __forceinline__ void issue_a_stage(char* smem, int kb, int buf, int n0, int N, int tid) {
    uint32_t abase = smem_u32(smem + SMEM_A + buf * 32768);
    const char* hsrc = (const char*)g_h_hi;
    const char* lsrc = (const char*)g_h_lo;
#pragma unroll
    for (int it = 0; it < 2; it++) {
        int idx = tid + 512 * it;           // 1024 chunks
        int row = idx >> 3, c = idx & 7;
        int n = n0 + row;
        uint32_t sz = (n < N) ? 16u : 0u;
        size_t so = (size_t)(n < N ? n : 0) * 512 + kb * 128 + c * 16;
        uint32_t ci = (uint32_t)(row * 8 + (c ^ (row & 7))) * 16;
        cp_async16(abase + ci, hsrc + so, sz);
        cp_async16(abase + 16384 + ci, lsrc + so, sz);
    }
}

__global__ __launch_bounds__(512, 1) void layer_kernel(int sel, int layer, int N) {
    extern __shared__ char smem[];
    const uint32_t sb = smem_u32(smem);
    const int tid = threadIdx.x;
    const int wid = tid >> 5;
    const int lid = tid & 31;
    const int n0 = blockIdx.x * 128;
    const int wm = wid & 3;        // rows wm*32
    const int wn = wid >> 2;       // cols wn*32

    // ---- resident B (full layer W, hi+lo, 128KB) + A stages ----
    {
        const char* wh = (const char*)(g_wbf_hi) + (size_t)layer * 65536;
        const char* wl = (const char*)(g_wbf_lo) + (size_t)layer * 65536;
        uint32_t bh = sb + SMEM_B_HI, bl = sb + SMEM_B_LO;
#pragma unroll
        for (int it = 0; it < 8; it++) {
            int idx = tid + 512 * it;       // 4096 chunks: [kb 4][row 128][c 8]
            int kb = idx >> 10;
            int r = (idx >> 3) & 127;
            int c = idx & 7;
            size_t so = (size_t)r * 512 + kb * 128 + c * 16;
            uint32_t ci = (uint32_t)(kb * 16384) + (uint32_t)(r * 8 + (c ^ (r & 7))) * 16;
            cp_async16(bh + ci, wh + so, 16);
            cp_async16(bl + ci, wl + so, 16);
        }
    }
    issue_a_stage(smem, 0, 0, n0, N, tid);
    CP_COMMIT();
    issue_a_stage(smem, 1, 1, n0, N, tid);
    CP_COMMIT();

    float acc[2][4][4];
#pragma unroll
    for (int mt = 0; mt < 2; mt++)
#pragma unroll
        for (int nt = 0; nt < 4; nt++)
#pragma unroll
            for (int c = 0; c < 4; c++) acc[mt][nt][c] = 0.f;

#pragma unroll
    for (int kb = 0; kb < 4; kb++) {
        if (kb < 3) CP_WAIT1(); else CP_WAIT0();
        __syncthreads();

        uint32_t abase = sb + SMEM_A + (kb & 1) * 32768;
        uint32_t bhbase = sb + SMEM_B_HI + kb * 16384;
        uint32_t blbase = sb + SMEM_B_LO + kb * 16384;
#pragma unroll
        for (int ks = 0; ks < 4; ks++) {
            uint32_t ahi[2][4], alo[2][4];
            int lr = lid & 15, lk = lid >> 4;
#pragma unroll
            for (int mt = 0; mt < 2; mt++) {
                int r = wm * 32 + mt * 16 + lr;
                int kc = ks * 2 + lk;
                uint32_t off = (uint32_t)(r * 8 + (kc ^ (r & 7))) * 16;
                LDSM_X4(ahi[mt], abase + off);
                LDSM_X4(alo[mt], abase + 16384 + off);
            }
            uint32_t bhi[2][4], blo[2][4];
            int nr = (lid & 7) + ((lid >> 4) << 3);
            int nk = (lid >> 3) & 1;
#pragma unroll
            for (int np = 0; np < 2; np++) {
                int r = wn * 32 + np * 16 + nr;
                int kc = ks * 2 + nk;
                uint32_t off = (uint32_t)(r * 8 + (kc ^ (r & 7))) * 16;
                LDSM_X4(bhi[np], bhbase + off);
                LDSM_X4(blo[np], blbase + off);
            }
#pragma unroll
            for (int mt = 0; mt < 2; mt++)
#pragma unroll
                for (int nt = 0; nt < 4; nt++) {
                    const uint32_t* bh = &bhi[nt >> 1][(nt & 1) * 2];
                    const uint32_t* bl = &blo[nt >> 1][(nt & 1) * 2];
                    mma16816(acc[mt][nt], ahi[mt], bh);
                    mma16816(acc[mt][nt], ahi[mt], bl);
                    mma16816(acc[mt][nt], alo[mt], bh);
                }
        }
        __syncthreads();
        if (kb + 2 < 4) { issue_a_stage(smem, kb + 2, kb & 1, n0, N, tid); CP_COMMIT(); }
    }

    // ================= epilogue (reuses B SMEM region) =================
    float* stage = (float*)smem;                      // [128][136]
    float* rowpart = (float*)(smem + EPI_ROWPART);    // [128][4]
    const float* bias = g_bias + layer * 128;
    int qid = lid >> 2, qt = lid & 3;
#pragma unroll
    for (int mt = 0; mt < 2; mt++) {
        int rA = wm * 32 + mt * 16 + qid;
        int rB = rA + 8;
        float sqa = 0.f, sqb = 0.f;
#pragma unroll
        for (int nt = 0; nt < 4; nt++) {
            int col = wn * 32 + nt * 8 + 2 * qt;
            float b0 = __ldg(bias + col), b1 = __ldg(bias + col + 1);
            float* c = acc[mt][nt];
            float x0 = c[0] + b0, x1 = c[1] + b1;
            float y0 = c[2] + b0, y1 = c[3] + b1;
            x0 = x0 > 0.f ? x0 : 0.2f * x0;
            x1 = x1 > 0.f ? x1 : 0.2f * x1;
            y0 = y0 > 0.f ? y0 : 0.2f * y0;
            y1 = y1 > 0.f ? y1 : 0.2f * y1;
            stage[rA * 136 + col] = x0;
            stage[rA * 136 + col + 1] = x1;
            stage[rB * 136 + col] = y0;
            stage[rB * 136 + col + 1] = y1;
            sqa += x0 * x0 + x1 * x1;
            sqb += y0 * y0 + y1 * y1;
        }
        sqa += __shfl_xor_sync(0xffffffffu, sqa, 1);
        sqa += __shfl_xor_sync(0xffffffffu, sqa, 2);
        sqb += __shfl_xor_sync(0xffffffffu, sqb, 1);
        sqb += __shfl_xor_sync(0xffffffffu, sqb, 2);
        if (qt == 0) {
            rowpart[rA * 4 + wn] = sqa;
            rowpart[rB * 4 + wn] = sqb;
        }
    }
    __syncthreads();
    float* scl = (float*)(smem + EPI_SCALE);
    if (tid < 128) {
        float tot = rowpart[tid * 4] + rowpart[tid * 4 + 1] + rowpart[tid * 4 + 2] + rowpart[tid * 4 + 3];
        scl[tid] = 1.0f / fmaxf(sqrtf(tot), 1e-12f);
    }
    __syncthreads();
    float* ego_out = g_ego[sel ^ 1];
    int seg = (layer + 1) * 128;
#pragma unroll
    for (int it = 0; it < 8; it++) {
        int idx = tid + 512 * it;           // [128 rows][32 f4]
        int r = idx >> 5, j = idx & 31;
        int n = n0 + r;
        if (n < N) {
            float4 v = *(const float4*)(stage + r * 136 + j * 4);
            ((float4*)(ego_out + (size_t)n * DIM))[j] = v;
            float s = scl[r];
            float4 sv = make_float4(v.x * s, v.y * s, v.z * s, v.w * s);
            ((float4*)(g_all + (size_t)n * 512 + seg))[j] = sv;
        }
    }
}

// ---------------- scoring ----------------
__global__ void score_kernel(const int* __restrict__ eli, float* __restrict__ out, int Q) {
    int g = blockIdx.x * blockDim.x + threadIdx.x;
    int q = g >> 5;
    if (q >= Q) return;
    int lane = g & 31;
    int s = __ldg(eli + q);
    int d = __ldg(eli + Q + q);
    const float4* ps = (const float4*)(g_all + (size_t)s * 512);
    const float4* pd = (const float4*)(g_all + (size_t)d * 512);
    float sum = 0.f;
#pragma unroll
    for (int t = 0; t < 4; t++) {
        float4 a = __ldg(ps + lane + 32 * t);
        float4 b = __ldg(pd + lane + 32 * t);
        sum += a.x * b.x + a.y * b.y + a.z * b.z + a.w * b.w;
    }
#pragma unroll
    for (int off = 16; off > 0; off >>= 1)
        sum += __shfl_xor_sync(0xffffffffu, sum, off);
    if (lane == 0) out[q] = sum;
}

// ---------------- launch ----------------
extern "C" void kernel_launch(void* const* d_in, const int* in_sizes, int n_in,
                              void* d_out, int out_size) {
    const int*   ei  = (const int*)d_in[0];
    const int*   eli = (const int*)d_in[1];
    const float* wt  = (const float*)d_in[2];
    const float* emb = (const float*)d_in[3];
    const float* gcw = (const float*)d_in[4];
    const float* gcb = (const float*)d_in[5];
    const float* biw = (const float*)d_in[6];
    const float* bib = (const float*)d_in[7];

    int E = in_sizes[2];
    int Q = in_sizes[1] / 2;
    int N = in_sizes[3] / DIM;

    static bool attr_set = false;
    if (!attr_set) {
        cudaFuncSetAttribute(layer_kernel, cudaFuncAttributeMaxDynamicSharedMemorySize, LK_SMEM);
        attr_set = true;
    }

    prep_kernel<<<(3 * 128 * 256 + 255) / 256, 256>>>(gcw, gcb, biw, bib);
    init_kernel<<<(N * 32 + 255) / 256, 256>>>(emb, N);

    int nblk = (N + 1023) / 1024;
    csr_zero_kernel<<<128, 256>>>(N);
    csr_hist_kernel<<<512, 256>>>(ei, E);
    csr_scan_local_kernel<<<nblk, 1024>>>(N);
    csr_scan_bsum_kernel<<<1, 256>>>(nblk);
    csr_scan_add_kernel<<<(N + 255) / 256, 256>>>(N);
    csr_fill_kernel<<<1024, 256>>>(ei, wt, E);

    int sel = 0;
    for (int i = 0; i < 3; i++) {
        long long gthreads = (long long)N * 32;
        int gblocks = (int)((gthreads + 255) / 256);
        gather_kernel<<<gblocks, 256>>>(sel, N);
        layer_kernel<<<(N + 127) / 128, 512, LK_SMEM>>>(sel, i, N);
        sel ^= 1;
    }
    score_kernel<<<(Q * 32 + 255) / 256, 256>>>(eli, (float*)d_out, Q);
}